// round 14
// baseline (speedup 1.0000x reference)
#include <cuda_runtime.h>
#include <cuda_fp16.h>
#include <math.h>
#include <stdint.h>

#define BQ 131072

// ---------------- scratch (device globals; no allocations) ----------------
__device__ __half g_emb[(size_t)BQ * 128];      // emb fp16, k padded to 128 (pads zeroed)
__device__ __half g_h1[(size_t)4 * BQ * 256];   // expert1 pre-act; later reused as t2_pre [8][BQ][128]
__device__ __half g_fea[(size_t)4 * BQ * 128];  // expert2 pre-act, stride 128 (113 valid)
__device__ __half g_task[(size_t)8 * BQ * 128]; // mixed task, stride 128 (113 valid, pad zeroed)
__device__ __half g_t1[(size_t)8 * BQ * 256];   // tower1 pre-act
// transposed fp16 weights, [slice][n][k] with pads zeroed
__device__ __half g_We1t[(size_t)4 * 256 * 128];
__device__ __half g_We2t[(size_t)4 * 128 * 256];
__device__ __half g_Wt1t[(size_t)8 * 256 * 128];
__device__ __half g_Wt2t[(size_t)8 * 128 * 256];
__device__ float g_stats[8][2048];              // per stage: [2s]=sum, [2s+1]=sumsq
__device__ __align__(16) float g_bnA[4][2048];  // folded BN scale (stages 1,3)
__device__ __align__(16) float g_bnC[4][2048];  // folded BN shift
__device__ int g_domIsI64;

// ---------------- helpers ----------------
__device__ __forceinline__ uint32_t h2u(half2 h) { return *(uint32_t*)&h; }
__device__ __forceinline__ void mma_f16(float* c, const uint32_t* a, const uint32_t* b) {
    asm volatile(
        "mma.sync.aligned.m16n8k16.row.col.f32.f16.f16.f32 "
        "{%0,%1,%2,%3}, {%4,%5,%6,%7}, {%8,%9}, {%0,%1,%2,%3};"
        : "+f"(c[0]), "+f"(c[1]), "+f"(c[2]), "+f"(c[3])
        : "r"(a[0]), "r"(a[1]), "r"(a[2]), "r"(a[3]), "r"(b[0]), "r"(b[1]));
}
__device__ __forceinline__ void ldsm4(uint32_t* r, uint32_t saddr) {
    asm volatile("ldmatrix.sync.aligned.m8n8.x4.shared.b16 {%0,%1,%2,%3}, [%4];"
        : "=r"(r[0]), "=r"(r[1]), "=r"(r[2]), "=r"(r[3]) : "r"(saddr));
}
__device__ __forceinline__ uint32_t smem_addr(const void* p) {
    return (uint32_t)__cvta_generic_to_shared(p);
}
#define CP_ASYNC16(dst, src) \
    asm volatile("cp.async.ca.shared.global [%0], [%1], 16;" :: "r"(dst), "l"(src) : "memory")
#define CP_COMMIT() asm volatile("cp.async.commit_group;" ::: "memory")
#define CP_WAIT0()  asm volatile("cp.async.wait_group 0;" ::: "memory")

// smem: As[2][128][36] words, Bs[2][128][36] words, BN 512, sums 256
#define T_W (128 * 36)
#define ROWB 144                 // row stride bytes
#define SMEM_BYTES ((4 * T_W + 512 + 256) * 4)

// ======================================================================
// fp16 GEMM, K-chunk 64, MITER m-tiles per CTA with continuous pipeline.
// C[s][m][n0+n] = sum_k f(A[s][m][k]) * Wt[s][n][k] + bias[s][n]
// B tiles identical across m-tiles; when NC==2 B is loaded only for mt=0.
// PREOP: f = BN+ReLU inline; A goes through LDG staging ONLY (no cp.async
// on the A buffer — the round-13 double-write race).
// Tile M=128 N=128, 256 thr (8 warps 2x4, warp 64x32), double-buffered.
// ======================================================================
template<int MITER, bool PREOP, bool SELSTORE>
__global__ void __launch_bounds__(256, 2) gemm_f16(
    const __half* __restrict__ A, long long aSS, int ldA, int KDIM,
    const __half* __restrict__ Wh, long long wSS, int ldK,
    const float* __restrict__ bias,
    const float* __restrict__ gamma, const float* __restrict__ beta,
    int statPrev, float invB,
    __half* __restrict__ C, long long cSS, int ldC,
    int Nfeat, int statStage, const int* __restrict__ dom)
{
    extern __shared__ char dsm[];
    uint32_t* smw = (uint32_t*)dsm;
    uint32_t (*As)[128][36] = (uint32_t(*)[128][36])smw;
    uint32_t (*Bs)[128][36] = (uint32_t(*)[128][36])(smw + 2 * T_W);
    float* sBNa = (float*)(smw + 4 * T_W);
    float* sBNc = sBNa + 256;
    float* sSum = (float*)(smw + 4 * T_W + 512);
    float* sSq  = sSum + 128;

    const int tid = threadIdx.x;
    const int wid = tid >> 5, lane = tid & 31;
    const int wm = wid & 1, wn = wid >> 1;
    const int lr = lane >> 2, lc = lane & 3;
    const int ln7 = lane & 7;

    const int s   = blockIdx.z;
    const int n0  = blockIdx.x * 128;
    const int mT0 = blockIdx.y * MITER;           // first m-tile index
    const int nvalid = min(128, Nfeat - n0);
    const int NC = KDIM >> 6;

    const __half* Asl = A + (long long)s * aSS;
    const __half* Wsl = Wh + (long long)s * wSS;

    if (tid < 128) { sSum[tid] = 0.f; sSq[tid] = 0.f; }
    if (PREOP) {
        for (int i = tid; i < KDIM; i += 256) {
            float m = g_stats[2 * statPrev][s * KDIM + i] * invB;
            float v = g_stats[2 * statPrev + 1][s * KDIM + i] * invB - m * m;
            float sc = gamma[s * KDIM + i] * rsqrtf(v + 1e-5f);
            sBNa[i] = sc;
            sBNc[i] = beta[s * KDIM + i] - m * sc;
        }
    }

    // ldmatrix per-lane base byte offsets (buffer 0)
    const uint32_t aBase = smem_addr(As) +
        (uint32_t)((wm * 64 + ln7 + ((lane >> 3) & 1) * 8) * ROWB + (lane >> 4) * 16);
    const uint32_t bBase = smem_addr(Bs) +
        (uint32_t)((wn * 32 + ln7 + (lane >> 4) * 8) * ROWB + ((lane >> 3) & 1) * 16);

    uint4 aRegH[4];   // PREOP staging

    auto issueA = [&](int mt, int c, int buf) {
        const int k0 = c * 64;
        const __half* Am = Asl + (long long)(mT0 + mt) * 128 * ldA;
#pragma unroll
        for (int p = 0; p < 4; p++) {
            int id = tid + p * 256;
            int row = id >> 3, q = id & 7;
            CP_ASYNC16(smem_addr(&As[buf][row][q * 4]),
                       Am + (long long)row * ldA + k0 + q * 8);
        }
    };
    auto issueB = [&](int c, int buf) {
        const int k0 = c * 64;
#pragma unroll
        for (int p = 0; p < 4; p++) {
            int id = tid + p * 256;
            int row = id >> 3, q = id & 7;
            CP_ASYNC16(smem_addr(&Bs[buf][row][q * 4]),
                       Wsl + (long long)(n0 + row) * ldK + k0 + q * 8);
        }
    };
    auto prefA = [&](int mt, int c) {
        const int k0 = c * 64;
        const __half* Am = Asl + (long long)(mT0 + mt) * 128 * ldA;
#pragma unroll
        for (int p = 0; p < 4; p++) {
            int id = tid + p * 256;
            int row = id >> 3, q = id & 7;
            aRegH[p] = *(const uint4*)(Am + (long long)row * ldA + k0 + q * 8);
        }
    };
    auto stsA = [&](int buf, int c) {
        const int k0 = c * 64;
#pragma unroll
        for (int p = 0; p < 4; p++) {
            int id = tid + p * 256;
            int row = id >> 3, q = id & 7;
            uint4 u = aRegH[p];
            const int kb = k0 + q * 8;
            uint32_t w[4] = { u.x, u.y, u.z, u.w };
#pragma unroll
            for (int j = 0; j < 4; j++) {
                float2 xf = __half22float2(*(half2*)&w[j]);
                float2 av = *(const float2*)&sBNa[kb + 2 * j];
                float2 cv = *(const float2*)&sBNc[kb + 2 * j];
                xf.x = fmaxf(fmaf(xf.x, av.x, cv.x), 0.f);
                xf.y = fmaxf(fmaf(xf.y, av.y, cv.y), 0.f);
                w[j] = h2u(__floats2half2_rn(xf.x, xf.y));
            }
            u.x = w[0]; u.y = w[1]; u.z = w[2]; u.w = w[3];
            *(uint4*)&As[buf][row][q * 4] = u;
        }
    };

    // bias once (registers)
    float bb[4][2];
#pragma unroll
    for (int ni = 0; ni < 4; ni++) {
        int cl = wn * 32 + ni * 8 + lc * 2;
        bb[ni][0] = (cl < nvalid) ? bias[(long long)s * Nfeat + n0 + cl] : 0.f;
        bb[ni][1] = (cl + 1 < nvalid) ? bias[(long long)s * Nfeat + n0 + cl + 1] : 0.f;
    }

    float acc[4][4][4];
#pragma unroll
    for (int mi = 0; mi < 4; mi++)
#pragma unroll
        for (int ni = 0; ni < 4; ni++)
#pragma unroll
            for (int q = 0; q < 4; q++) acc[mi][ni][q] = 0.f;

    // prologue: (mt=0, c=0) into buffer 0.  A via cp.async ONLY when !PREOP.
    if (PREOP) prefA(0, 0);
    else       issueA(0, 0, 0);
    issueB(0, 0);
    CP_COMMIT();
    if (PREOP) {
        __syncthreads();          // sBN ready
        stsA(0, 0);
    }
    CP_WAIT0();
    __syncthreads();

    int buf = 0;
    for (int mt = 0; mt < MITER; mt++) {
        for (int c = 0; c < NC; c++) {
            int nmt = mt, ncc = c + 1;
            if (ncc == NC) { ncc = 0; nmt++; }
            const bool more = nmt < MITER;
            if (more) {
                if (PREOP) prefA(nmt, ncc);
                else       issueA(nmt, ncc, buf ^ 1);     // FIXED: no async A on PREOP
                if (nmt == 0 || NC > 2) issueB(ncc, buf ^ 1);
                CP_COMMIT();
            }

            const uint32_t aOff = aBase + buf * (T_W * 4);
            const uint32_t bOff = bBase + buf * (T_W * 4);
#pragma unroll
            for (int ks = 0; ks < 4; ks++) {
                uint32_t af[4][4];
#pragma unroll
                for (int mi = 0; mi < 4; mi++)
                    ldsm4(af[mi], aOff + mi * (16 * ROWB) + ks * 32);
                uint32_t bf[2][4];
                ldsm4(bf[0], bOff + ks * 32);
                ldsm4(bf[1], bOff + 16 * ROWB + ks * 32);
#pragma unroll
                for (int mi = 0; mi < 4; mi++)
#pragma unroll
                    for (int ni = 0; ni < 4; ni++)
                        mma_f16(acc[mi][ni], af[mi], &bf[ni >> 1][(ni & 1) * 2]);
            }

            if (more && PREOP) stsA(buf ^ 1, ncc);

            if (c == NC - 1) {
                // ---- per-tile epilogue (overlaps in-flight cp.async) ----
                const int m0 = (mT0 + mt) * 128;
                float cs[4][2] = {{0,0},{0,0},{0,0},{0,0}};
                float cq[4][2] = {{0,0},{0,0},{0,0},{0,0}};
#pragma unroll
                for (int mi = 0; mi < 4; mi++) {
                    const int r0 = m0 + wm * 64 + mi * 16 + lr;
                    bool st0 = true, st1 = true;
                    if (SELSTORE) {
                        int d0 = g_domIsI64 ? (int)(((const long long*)dom)[r0])     : dom[r0];
                        int d1 = g_domIsI64 ? (int)(((const long long*)dom)[r0 + 8]) : dom[r0 + 8];
                        st0 = (d0 == s); st1 = (d1 == s);
                    }
#pragma unroll
                    for (int ni = 0; ni < 4; ni++) {
                        const int cl = wn * 32 + ni * 8 + lc * 2;
                        float v00 = acc[mi][ni][0] + bb[ni][0];
                        float v01 = acc[mi][ni][1] + bb[ni][1];
                        float v10 = acc[mi][ni][2] + bb[ni][0];
                        float v11 = acc[mi][ni][3] + bb[ni][1];
                        cs[ni][0] += v00 + v10;  cq[ni][0] += v00 * v00 + v10 * v10;
                        cs[ni][1] += v01 + v11;  cq[ni][1] += v01 * v01 + v11 * v11;
                        __half* p0 = C + (long long)s * cSS + (long long)r0 * ldC + n0 + cl;
                        __half* p1 = p0 + (long long)8 * ldC;
                        if (cl + 1 < nvalid) {
                            if (st0) *(half2*)p0 = __floats2half2_rn(v00, v01);
                            if (st1) *(half2*)p1 = __floats2half2_rn(v10, v11);
                        } else if (cl < nvalid) {
                            if (st0) *p0 = __float2half_rn(v00);
                            if (st1) *p1 = __float2half_rn(v10);
                        }
                        acc[mi][ni][0] = 0.f; acc[mi][ni][1] = 0.f;
                        acc[mi][ni][2] = 0.f; acc[mi][ni][3] = 0.f;
                    }
                }
#pragma unroll
                for (int ni = 0; ni < 4; ni++)
#pragma unroll
                    for (int h = 0; h < 2; h++) {
                        int cl = wn * 32 + ni * 8 + lc * 2 + h;
                        if (cl < nvalid) { atomicAdd(&sSum[cl], cs[ni][h]); atomicAdd(&sSq[cl], cq[ni][h]); }
                    }
            }

            if (more) {
                CP_WAIT0();
                __syncthreads();
                buf ^= 1;
            }
        }
    }

    // single global stats flush per CTA
    __syncthreads();
    if (tid < 128 && tid < nvalid) {
        atomicAdd(&g_stats[2 * statStage][s * Nfeat + n0 + tid], sSum[tid]);
        atomicAdd(&g_stats[2 * statStage + 1][s * Nfeat + n0 + tid], sSq[tid]);
    }
}

// ---------------- prep kernels ----------------
__global__ void prep_emb(const float* __restrict__ emb) {
    int g = blockIdx.x * 256 + threadIdx.x;
    int b = g >> 5, q = g & 31;
    int k = q * 4;
    const float* src = emb + (long long)b * 113;
    half2 h0 = __floats2half2_rn((k     < 113) ? src[k]     : 0.f,
                                 (k + 1 < 113) ? src[k + 1] : 0.f);
    half2 h1 = __floats2half2_rn((k + 2 < 113) ? src[k + 2] : 0.f,
                                 (k + 3 < 113) ? src[k + 3] : 0.f);
    uint2 st; st.x = h2u(h0); st.y = h2u(h1);
    *(uint2*)(g_emb + (long long)b * 128 + k) = st;
}
__global__ void prep_expert(const float* __restrict__ We1, const float* __restrict__ We2) {
    int i = blockIdx.x * 256 + threadIdx.x;
    int s = blockIdx.y;
    if (blockIdx.z == 0) {
        int n = i >> 7, k = i & 127;
        g_We1t[(size_t)s * 32768 + i] =
            (k < 113) ? __float2half_rn(We1[((long long)s * 113 + k) * 256 + n]) : __half(0);
        if (s == 0 && i < 16384) ((float*)g_stats)[i] = 0.f;
    } else {
        int n = i >> 8, k = i & 255;
        g_We2t[(size_t)s * 32768 + i] =
            (n < 113) ? __float2half_rn(We2[((long long)s * 256 + k) * 113 + n]) : __half(0);
    }
}
__global__ void prep_tower(const float* __restrict__ Wt1, const float* __restrict__ Wt2,
                           const int* __restrict__ dom) {
    int i = blockIdx.x * 256 + threadIdx.x;
    int s = blockIdx.y;
    if (blockIdx.z == 0) {
        int n = i >> 7, k = i & 127;
        g_Wt1t[(size_t)s * 32768 + i] =
            (k < 113) ? __float2half_rn(Wt1[((long long)s * 113 + k) * 256 + n]) : __half(0);
        if (s == 0 && i == 0) {
            const long long* d64 = (const long long*)dom;
            bool ok = true;
            for (int j = 0; j < 64; j++) {
                long long v = d64[j];
                if (v < 0 || v >= 8) ok = false;
            }
            g_domIsI64 = ok ? 1 : 0;
        }
    } else {
        int n = i >> 8, k = i & 255;
        g_Wt2t[(size_t)s * 32768 + i] =
            __float2half_rn(Wt2[((long long)s * 256 + k) * 128 + n]);
    }
}

__global__ void finalize_kernel(int stage, const float* __restrict__ gamma,
                                const float* __restrict__ beta, int n, float invB) {
    int i = blockIdx.x * blockDim.x + threadIdx.x;
    if (i < n) {
        float m = g_stats[2 * stage][i] * invB;
        float v = g_stats[2 * stage + 1][i] * invB - m * m;
        float sc = gamma[i] / sqrtf(v + 1e-5f);
        g_bnA[stage][i] = sc;
        g_bnC[stage][i] = beta[i] - m * sc;
    }
}

// gates + BN/ReLU(fea fp16) + mixture -> task fp16 (stride 128, pad zeroed)
__global__ void gates_task_kernel(const float* __restrict__ emb,
                                  const float* __restrict__ Wg,
                                  const float* __restrict__ bg,
                                  const __half* __restrict__ fea_pre,
                                  __half* __restrict__ task, int B) {
    __shared__ float s_emb[113];
    __shared__ float s_g[8][4];
    const int b = blockIdx.x;
    const int tid = threadIdx.x;
    if (tid < 113) s_emb[tid] = emb[(long long)b * 113 + tid];
    __syncthreads();
    if (tid < 32) {
        int d = tid >> 2, e = tid & 3;
        float acc = bg[d * 4 + e];
        const float* w = Wg + d * 113 * 4 + e;
        for (int i = 0; i < 113; i++) acc = fmaf(s_emb[i], w[i * 4], acc);
        s_g[d][e] = acc;
    }
    __syncthreads();
    if (tid < 8) {
        float g0 = s_g[tid][0], g1 = s_g[tid][1], g2 = s_g[tid][2], g3 = s_g[tid][3];
        float m = fmaxf(fmaxf(g0, g1), fmaxf(g2, g3));
        float e0 = expf(g0 - m), e1 = expf(g1 - m), e2 = expf(g2 - m), e3 = expf(g3 - m);
        float inv = 1.f / (e0 + e1 + e2 + e3);
        s_g[tid][0] = e0 * inv; s_g[tid][1] = e1 * inv;
        s_g[tid][2] = e2 * inv; s_g[tid][3] = e3 * inv;
    }
    __syncthreads();
    if (tid < 113) {
        float fe[4];
#pragma unroll
        for (int e = 0; e < 4; e++) {
            float x = __half2float(fea_pre[((long long)e * B + b) * 128 + tid]);
            fe[e] = fmaxf(fmaf(x, g_bnA[1][e * 113 + tid], g_bnC[1][e * 113 + tid]), 0.f);
        }
#pragma unroll
        for (int d = 0; d < 8; d++) {
            float t = s_g[d][0] * fe[0] + s_g[d][1] * fe[1] + s_g[d][2] * fe[2] + s_g[d][3] * fe[3];
            task[((long long)d * B + b) * 128 + tid] = __float2half_rn(t);
        }
    } else {
#pragma unroll
        for (int d = 0; d < 8; d++)
            task[((long long)d * B + b) * 128 + tid] = __float2half_rn(0.f);
    }
}

// final: per b, pick domain tower, BN+ReLU on t2 (fp16), dot Wt3, sigmoid
__global__ void final_kernel(const __half* __restrict__ t2,
                             const float* __restrict__ Wt3,
                             const float* __restrict__ bt3,
                             const int* __restrict__ dom,
                             float* __restrict__ out, int B) {
    int gid = blockIdx.x * blockDim.x + threadIdx.x;
    int b = gid >> 5, lane = gid & 31;
    if (b >= B) return;
    int d = g_domIsI64 ? (int)(((const long long*)dom)[b]) : dom[b];
    uint2 u = reinterpret_cast<const uint2*>(t2 + ((long long)d * B + b) * 128)[lane];
    float2 x01 = __half22float2(*(half2*)&u.x);
    float2 x23 = __half22float2(*(half2*)&u.y);
    float4 aa = *reinterpret_cast<const float4*>(&g_bnA[3][d * 128 + lane * 4]);
    float4 cc = *reinterpret_cast<const float4*>(&g_bnC[3][d * 128 + lane * 4]);
    float4 w  = reinterpret_cast<const float4*>(Wt3 + d * 128)[lane];
    float s = fmaxf(fmaf(x01.x, aa.x, cc.x), 0.f) * w.x
            + fmaxf(fmaf(x01.y, aa.y, cc.y), 0.f) * w.y
            + fmaxf(fmaf(x23.x, aa.z, cc.z), 0.f) * w.z
            + fmaxf(fmaf(x23.y, aa.w, cc.w), 0.f) * w.w;
#pragma unroll
    for (int o = 16; o; o >>= 1) s += __shfl_xor_sync(0xffffffffu, s, o);
    if (lane == 0) out[b] = 1.f / (1.f + expf(-(s + bt3[d])));
}

// ---------------- host ----------------
extern "C" void kernel_launch(void* const* d_in, const int* in_sizes, int n_in,
                              void* d_out, int out_size) {
    const int B = 131072;
    int domIdx = -1;
    for (int i = 0; i < n_in; i++)
        if (in_sizes[i] == B) { domIdx = i; break; }

    const float* ptrs[21];
    int pi = 0;
    for (int i = 0; i < n_in && pi < 21; i++) {
        if (i == domIdx) continue;
        ptrs[pi++] = (const float*)d_in[i];
    }
    const float* emb = ptrs[0];
    const float* We1 = ptrs[1],  *be1 = ptrs[2],  *eg1 = ptrs[3],  *eb1 = ptrs[4];
    const float* We2 = ptrs[5],  *be2 = ptrs[6],  *eg2 = ptrs[7],  *eb2 = ptrs[8];
    const float* Wg  = ptrs[9],  *bg  = ptrs[10];
    const float* Wt1 = ptrs[11], *bt1 = ptrs[12], *tg1 = ptrs[13], *tb1 = ptrs[14];
    const float* Wt2 = ptrs[15], *bt2 = ptrs[16], *tg2 = ptrs[17], *tb2 = ptrs[18];
    const float* Wt3 = ptrs[19], *bt3 = ptrs[20];
    const int* dom = (const int*)d_in[domIdx];
    float* out = (float*)d_out;

    __half *p_emb, *p_h1, *p_fea, *p_task, *p_t1, *p_We1t, *p_We2t, *p_Wt1t, *p_Wt2t;
    cudaGetSymbolAddress((void**)&p_emb, g_emb);
    cudaGetSymbolAddress((void**)&p_h1,  g_h1);
    cudaGetSymbolAddress((void**)&p_fea, g_fea);
    cudaGetSymbolAddress((void**)&p_task, g_task);
    cudaGetSymbolAddress((void**)&p_t1,  g_t1);
    cudaGetSymbolAddress((void**)&p_We1t, g_We1t);
    cudaGetSymbolAddress((void**)&p_We2t, g_We2t);
    cudaGetSymbolAddress((void**)&p_Wt1t, g_Wt1t);
    cudaGetSymbolAddress((void**)&p_Wt2t, g_Wt2t);

    cudaFuncSetAttribute(gemm_f16<4, false, false>, cudaFuncAttributeMaxDynamicSharedMemorySize, SMEM_BYTES);
    cudaFuncSetAttribute(gemm_f16<4, true,  false>, cudaFuncAttributeMaxDynamicSharedMemorySize, SMEM_BYTES);
    cudaFuncSetAttribute(gemm_f16<4, true,  true >, cudaFuncAttributeMaxDynamicSharedMemorySize, SMEM_BYTES);

    const float invB = 1.f / (float)B;
    const int MY = B / (128 * 4);   // 256 m-groups

    // (1)(2)(3) prep
    prep_emb<<<(B * 32) / 256, 256>>>(emb);
    prep_expert<<<dim3(128, 4, 2), 256>>>(We1, We2);
    prep_tower<<<dim3(128, 8, 2), 256>>>(Wt1, Wt2, dom);

    // (4) expert layer 1: g_emb x We1t -> h1 fp16   <-- ncu lands here
    gemm_f16<4, false, false><<<dim3(2, MY, 4), 256, SMEM_BYTES>>>(
        p_emb, 0LL, 128, 128, p_We1t, 32768LL, 128, be1,
        nullptr, nullptr, 0, invB, p_h1, (long long)B * 256, 256, 256, 0, nullptr);

    // (5) expert layer 2 (inline BN0): BN+ReLU(h1) x We2t -> fea fp16
    gemm_f16<4, true, false><<<dim3(1, MY, 4), 256, SMEM_BYTES>>>(
        p_h1, (long long)B * 256, 256, 256, p_We2t, 32768LL, 256, be2,
        eg1, eb1, 0, invB, p_fea, (long long)B * 128, 128, 113, 1, nullptr);

    // (6) finalize stage 1 (consumed elementwise by gates)
    finalize_kernel<<<2, 256>>>(1, eg2, eb2, 4 * 113, invB);

    // (7) gates + mixture -> task fp16
    gates_task_kernel<<<B, 128>>>(emb, Wg, bg, p_fea, p_task, B);

    // (8) tower layer 1: task x Wt1t -> t1 fp16
    gemm_f16<4, false, false><<<dim3(2, MY, 8), 256, SMEM_BYTES>>>(
        p_task, (long long)B * 128, 128, 128, p_Wt1t, 32768LL, 128, bt1,
        nullptr, nullptr, 0, invB, p_t1, (long long)B * 256, 256, 256, 2, nullptr);

    // (9) tower layer 2 (inline BN2, selective store): BN+ReLU(t1) x Wt2t -> t2 (reuses g_h1)
    gemm_f16<4, true, true><<<dim3(1, MY, 8), 256, SMEM_BYTES>>>(
        p_t1, (long long)B * 256, 256, 256, p_Wt2t, 32768LL, 256, bt2,
        tg1, tb1, 2, invB, p_h1, (long long)B * 128, 128, 128, 3, dom);

    // (10) finalize stage 3 (consumed elementwise by final)
    finalize_kernel<<<4, 256>>>(3, tg2, tb2, 8 * 128, invB);

    // (11) final
    final_kernel<<<(B * 32) / 256, 256>>>(p_h1, Wt3, bt3, dom, out, B);
}

// round 15
// speedup vs baseline: 1.0454x; 1.0454x over previous
#include <cuda_runtime.h>
#include <cuda_fp16.h>
#include <math.h>
#include <stdint.h>

#define BQ 131072

// ---------------- scratch (device globals; no allocations) ----------------
__device__ __half g_emb[(size_t)BQ * 128];      // emb fp16, k padded to 128 (pads zeroed)
__device__ __half g_h1[(size_t)4 * BQ * 256];   // expert1 pre-act; later reused as t2_pre [8][BQ][128]
__device__ __half g_fea[(size_t)4 * BQ * 128];  // expert2 pre-act, stride 128 (113 valid)
__device__ __half g_task[(size_t)8 * BQ * 128]; // mixed task, stride 128 (113 valid, pad zeroed)
__device__ __half g_t1[(size_t)8 * BQ * 256];   // tower1 pre-act
// transposed fp16 weights, [slice][n][k] with pads zeroed
__device__ __half g_We1t[(size_t)4 * 256 * 128];
__device__ __half g_We2t[(size_t)4 * 128 * 256];
__device__ __half g_Wt1t[(size_t)8 * 256 * 128];
__device__ __half g_Wt2t[(size_t)8 * 128 * 256];
__device__ float g_stats[8][2048];              // per stage: [2s]=sum, [2s+1]=sumsq
__device__ __align__(16) float g_bnA[4][2048];  // folded BN scale (stages 1,3)
__device__ __align__(16) float g_bnC[4][2048];  // folded BN shift
__device__ int g_domIsI64;

// ---------------- helpers ----------------
__device__ __forceinline__ uint32_t h2u(half2 h) { return *(uint32_t*)&h; }
__device__ __forceinline__ void mma_f16(float* c, const uint32_t* a, const uint32_t* b) {
    asm volatile(
        "mma.sync.aligned.m16n8k16.row.col.f32.f16.f16.f32 "
        "{%0,%1,%2,%3}, {%4,%5,%6,%7}, {%8,%9}, {%0,%1,%2,%3};"
        : "+f"(c[0]), "+f"(c[1]), "+f"(c[2]), "+f"(c[3])
        : "r"(a[0]), "r"(a[1]), "r"(a[2]), "r"(a[3]), "r"(b[0]), "r"(b[1]));
}
__device__ __forceinline__ void ldsm4(uint32_t* r, uint32_t saddr) {
    asm volatile("ldmatrix.sync.aligned.m8n8.x4.shared.b16 {%0,%1,%2,%3}, [%4];"
        : "=r"(r[0]), "=r"(r[1]), "=r"(r[2]), "=r"(r[3]) : "r"(saddr));
}
__device__ __forceinline__ uint32_t smem_addr(const void* p) {
    return (uint32_t)__cvta_generic_to_shared(p);
}
#define CP_ASYNC16(dst, src) \
    asm volatile("cp.async.ca.shared.global [%0], [%1], 16;" :: "r"(dst), "l"(src) : "memory")
#define CP_COMMIT() asm volatile("cp.async.commit_group;" ::: "memory")
#define CP_WAIT0()  asm volatile("cp.async.wait_group 0;" ::: "memory")

// smem: As[2][128][36] words, Bs[2][128][36] words, BN 512, sums 256
#define T_W (128 * 36)
#define ROWB 144                 // row stride bytes
#define SMEM_BYTES ((4 * T_W + 512 + 256) * 4)

// ======================================================================
// fp16 GEMM, K-chunk 64, cp.async fills (A via LDG staging when PREOP).
// (round-12 configuration — best measured)
// ======================================================================
template<bool PREOP, bool SELSTORE>
__global__ void __launch_bounds__(256, 2) gemm_f16(
    const __half* __restrict__ A, long long aSS, int ldA, int KDIM,
    const __half* __restrict__ Wh, long long wSS, int ldK,
    const float* __restrict__ bias,
    const float* __restrict__ gamma, const float* __restrict__ beta,
    int statPrev, float invB,
    __half* __restrict__ C, long long cSS, int ldC,
    int Nfeat, int statStage, const int* __restrict__ dom)
{
    extern __shared__ char dsm[];
    uint32_t* smw = (uint32_t*)dsm;
    uint32_t (*As)[128][36] = (uint32_t(*)[128][36])smw;
    uint32_t (*Bs)[128][36] = (uint32_t(*)[128][36])(smw + 2 * T_W);
    float* sBNa = (float*)(smw + 4 * T_W);
    float* sBNc = sBNa + 256;
    float* sSum = (float*)(smw + 4 * T_W + 512);
    float* sSq  = sSum + 128;

    const int tid = threadIdx.x;
    const int wid = tid >> 5, lane = tid & 31;
    const int wm = wid & 1, wn = wid >> 1;
    const int lr = lane >> 2, lc = lane & 3;
    const int ln7 = lane & 7;

    const int s  = blockIdx.z;
    const int n0 = blockIdx.x * 128;
    const int m0 = blockIdx.y * 128;
    const int nvalid = min(128, Nfeat - n0);
    const int NC = KDIM >> 6;

    const __half* Asl = A + (long long)s * aSS;
    const __half* Wsl = Wh + (long long)s * wSS;

    if (tid < 128) { sSum[tid] = 0.f; sSq[tid] = 0.f; }
    if (PREOP) {
        for (int i = tid; i < KDIM; i += 256) {
            float m = g_stats[2 * statPrev][s * KDIM + i] * invB;
            float v = g_stats[2 * statPrev + 1][s * KDIM + i] * invB - m * m;
            float sc = gamma[s * KDIM + i] * rsqrtf(v + 1e-5f);
            sBNa[i] = sc;
            sBNc[i] = beta[s * KDIM + i] - m * sc;
        }
    }

    const uint32_t aBase = smem_addr(As) +
        (uint32_t)((wm * 64 + ln7 + ((lane >> 3) & 1) * 8) * ROWB + (lane >> 4) * 16);
    const uint32_t bBase = smem_addr(Bs) +
        (uint32_t)((wn * 32 + ln7 + (lane >> 4) * 8) * ROWB + ((lane >> 3) & 1) * 16);

    uint4 aRegH[4];

    auto issueAsync = [&](int c, int buf) {
        const int k0 = c * 64;
        if (!PREOP) {
#pragma unroll
            for (int p = 0; p < 4; p++) {
                int id = tid + p * 256;
                int row = id >> 3, q = id & 7;
                CP_ASYNC16(smem_addr(&As[buf][row][q * 4]),
                           Asl + (long long)(m0 + row) * ldA + k0 + q * 8);
            }
        }
#pragma unroll
        for (int p = 0; p < 4; p++) {
            int id = tid + p * 256;
            int row = id >> 3, q = id & 7;
            CP_ASYNC16(smem_addr(&Bs[buf][row][q * 4]),
                       Wsl + (long long)(n0 + row) * ldK + k0 + q * 8);
        }
        CP_COMMIT();
    };
    auto prefA = [&](int c) {
        const int k0 = c * 64;
#pragma unroll
        for (int p = 0; p < 4; p++) {
            int id = tid + p * 256;
            int row = id >> 3, q = id & 7;
            aRegH[p] = *(const uint4*)(Asl + (long long)(m0 + row) * ldA + k0 + q * 8);
        }
    };
    auto stsA = [&](int buf, int c) {
        const int k0 = c * 64;
#pragma unroll
        for (int p = 0; p < 4; p++) {
            int id = tid + p * 256;
            int row = id >> 3, q = id & 7;
            uint4 u = aRegH[p];
            const int kb = k0 + q * 8;
            uint32_t w[4] = { u.x, u.y, u.z, u.w };
#pragma unroll
            for (int j = 0; j < 4; j++) {
                float2 xf = __half22float2(*(half2*)&w[j]);
                float2 av = *(const float2*)&sBNa[kb + 2 * j];
                float2 cv = *(const float2*)&sBNc[kb + 2 * j];
                xf.x = fmaxf(fmaf(xf.x, av.x, cv.x), 0.f);
                xf.y = fmaxf(fmaf(xf.y, av.y, cv.y), 0.f);
                w[j] = h2u(__floats2half2_rn(xf.x, xf.y));
            }
            u.x = w[0]; u.y = w[1]; u.z = w[2]; u.w = w[3];
            *(uint4*)&As[buf][row][q * 4] = u;
        }
    };

    float acc[4][4][4];
#pragma unroll
    for (int mi = 0; mi < 4; mi++)
#pragma unroll
        for (int ni = 0; ni < 4; ni++)
#pragma unroll
            for (int q = 0; q < 4; q++) acc[mi][ni][q] = 0.f;

    if (PREOP) prefA(0);
    issueAsync(0, 0);
    if (PREOP) {
        __syncthreads();
        stsA(0, 0);
    }
    CP_WAIT0();
    __syncthreads();

    for (int c = 0; c < NC; c++) {
        const int cur = c & 1;
        const bool more = (c + 1) < NC;
        if (more) {
            if (PREOP) prefA(c + 1);
            issueAsync(c + 1, cur ^ 1);
        }

        const uint32_t aOff = aBase + cur * (T_W * 4);
        const uint32_t bOff = bBase + cur * (T_W * 4);
#pragma unroll
        for (int ks = 0; ks < 4; ks++) {
            uint32_t af[4][4];
#pragma unroll
            for (int mi = 0; mi < 4; mi++)
                ldsm4(af[mi], aOff + mi * (16 * ROWB) + ks * 32);
            uint32_t bf[2][4];
            ldsm4(bf[0], bOff + ks * 32);
            ldsm4(bf[1], bOff + 16 * ROWB + ks * 32);
#pragma unroll
            for (int mi = 0; mi < 4; mi++)
#pragma unroll
                for (int ni = 0; ni < 4; ni++)
                    mma_f16(acc[mi][ni], af[mi], &bf[ni >> 1][(ni & 1) * 2]);
        }

        if (more) {
            if (PREOP) stsA(cur ^ 1, c + 1);
            CP_WAIT0();
            __syncthreads();
        }
    }

    // ---- epilogue: bias, stats, fp16 store ----
    float bb[4][2];
#pragma unroll
    for (int ni = 0; ni < 4; ni++) {
        int cl = wn * 32 + ni * 8 + lc * 2;
        bb[ni][0] = (cl < nvalid) ? bias[(long long)s * Nfeat + n0 + cl] : 0.f;
        bb[ni][1] = (cl + 1 < nvalid) ? bias[(long long)s * Nfeat + n0 + cl + 1] : 0.f;
    }
    float cs[4][2] = {{0,0},{0,0},{0,0},{0,0}};
    float cq[4][2] = {{0,0},{0,0},{0,0},{0,0}};

#pragma unroll
    for (int mi = 0; mi < 4; mi++) {
        const int r0 = m0 + wm * 64 + mi * 16 + lr;
        bool st0 = true, st1 = true;
        if (SELSTORE) {
            int d0 = g_domIsI64 ? (int)(((const long long*)dom)[r0])     : dom[r0];
            int d1 = g_domIsI64 ? (int)(((const long long*)dom)[r0 + 8]) : dom[r0 + 8];
            st0 = (d0 == s); st1 = (d1 == s);
        }
#pragma unroll
        for (int ni = 0; ni < 4; ni++) {
            const int cl = wn * 32 + ni * 8 + lc * 2;
            float v00 = acc[mi][ni][0] + bb[ni][0];
            float v01 = acc[mi][ni][1] + bb[ni][1];
            float v10 = acc[mi][ni][2] + bb[ni][0];
            float v11 = acc[mi][ni][3] + bb[ni][1];
            cs[ni][0] += v00 + v10;  cq[ni][0] += v00 * v00 + v10 * v10;
            cs[ni][1] += v01 + v11;  cq[ni][1] += v01 * v01 + v11 * v11;
            __half* p0 = C + (long long)s * cSS + (long long)r0 * ldC + n0 + cl;
            __half* p1 = p0 + (long long)8 * ldC;
            if (cl + 1 < nvalid) {
                if (st0) *(half2*)p0 = __floats2half2_rn(v00, v01);
                if (st1) *(half2*)p1 = __floats2half2_rn(v10, v11);
            } else if (cl < nvalid) {
                if (st0) *p0 = __float2half_rn(v00);
                if (st1) *p1 = __float2half_rn(v10);
            }
        }
    }
#pragma unroll
    for (int ni = 0; ni < 4; ni++)
#pragma unroll
        for (int h = 0; h < 2; h++) {
            int cl = wn * 32 + ni * 8 + lc * 2 + h;
            if (cl < nvalid) { atomicAdd(&sSum[cl], cs[ni][h]); atomicAdd(&sSq[cl], cq[ni][h]); }
        }
    __syncthreads();
    if (tid < 128 && tid < nvalid) {
        atomicAdd(&g_stats[2 * statStage][s * Nfeat + n0 + tid], sSum[tid]);
        atomicAdd(&g_stats[2 * statStage + 1][s * Nfeat + n0 + tid], sSq[tid]);
    }
}

// ---------------- prep kernels ----------------
__global__ void prep_emb(const float* __restrict__ emb) {
    int g = blockIdx.x * 256 + threadIdx.x;
    int b = g >> 5, q = g & 31;
    int k = q * 4;
    const float* src = emb + (long long)b * 113;
    half2 h0 = __floats2half2_rn((k     < 113) ? src[k]     : 0.f,
                                 (k + 1 < 113) ? src[k + 1] : 0.f);
    half2 h1 = __floats2half2_rn((k + 2 < 113) ? src[k + 2] : 0.f,
                                 (k + 3 < 113) ? src[k + 3] : 0.f);
    uint2 st; st.x = h2u(h0); st.y = h2u(h1);
    *(uint2*)(g_emb + (long long)b * 128 + k) = st;
}
__global__ void prep_expert(const float* __restrict__ We1, const float* __restrict__ We2) {
    int i = blockIdx.x * 256 + threadIdx.x;
    int s = blockIdx.y;
    if (blockIdx.z == 0) {
        int n = i >> 7, k = i & 127;
        g_We1t[(size_t)s * 32768 + i] =
            (k < 113) ? __float2half_rn(We1[((long long)s * 113 + k) * 256 + n]) : __half(0);
        if (s == 0 && i < 16384) ((float*)g_stats)[i] = 0.f;
    } else {
        int n = i >> 8, k = i & 255;
        g_We2t[(size_t)s * 32768 + i] =
            (n < 113) ? __float2half_rn(We2[((long long)s * 256 + k) * 113 + n]) : __half(0);
    }
}
__global__ void prep_tower(const float* __restrict__ Wt1, const float* __restrict__ Wt2,
                           const int* __restrict__ dom) {
    int i = blockIdx.x * 256 + threadIdx.x;
    int s = blockIdx.y;
    if (blockIdx.z == 0) {
        int n = i >> 7, k = i & 127;
        g_Wt1t[(size_t)s * 32768 + i] =
            (k < 113) ? __float2half_rn(Wt1[((long long)s * 113 + k) * 256 + n]) : __half(0);
        if (s == 0 && i == 0) {
            const long long* d64 = (const long long*)dom;
            bool ok = true;
            for (int j = 0; j < 64; j++) {
                long long v = d64[j];
                if (v < 0 || v >= 8) ok = false;
            }
            g_domIsI64 = ok ? 1 : 0;
        }
    } else {
        int n = i >> 8, k = i & 255;
        g_Wt2t[(size_t)s * 32768 + i] =
            __float2half_rn(Wt2[((long long)s * 256 + k) * 128 + n]);
    }
}

__global__ void finalize_kernel(int stage, const float* __restrict__ gamma,
                                const float* __restrict__ beta, int n, float invB) {
    int i = blockIdx.x * blockDim.x + threadIdx.x;
    if (i < n) {
        float m = g_stats[2 * stage][i] * invB;
        float v = g_stats[2 * stage + 1][i] * invB - m * m;
        float sc = gamma[i] / sqrtf(v + 1e-5f);
        g_bnA[stage][i] = sc;
        g_bnC[stage][i] = beta[i] - m * sc;
    }
}

// ======================================================================
// gates_task_v2: 8 samples per 256-thread block (1 warp per sample).
// Wg (113x32 fp32) staged ONCE per block in smem. emb from fp16 g_emb via
// register + shuffle broadcast. Softmax over e within 4-lane groups.
// Mixture with coalesced fea loads / task stores.  task stride 128, pads 0.
// ======================================================================
__global__ void __launch_bounds__(256) gates_task_v2(
    const __half* __restrict__ gemb,
    const float* __restrict__ Wg,   // [D=8][113][E=4]
    const float* __restrict__ bg,   // [8][4]
    const __half* __restrict__ fea, // [4][B][128]
    __half* __restrict__ task,      // [8][B][128]
    int B)
{
    __shared__ float sWg[113 * 32];   // [i][de], de = d*4+e
    __shared__ float sBg[32];
    __shared__ float sG[8][32];

    const int tid = threadIdx.x;
    for (int idx = tid; idx < 113 * 32; idx += 256) {
        int i = idx >> 5, de = idx & 31, d = de >> 2, e = de & 3;
        sWg[idx] = Wg[((long long)d * 113 + i) * 4 + e];
    }
    if (tid < 32) sBg[tid] = bg[tid];
    __syncthreads();

    const int w = tid >> 5, lane = tid & 31;
    const long long b = (long long)blockIdx.x * 8 + w;

    // emb: lane holds halves k = lane*4 .. lane*4+3
    uint2 eu = *(const uint2*)(gemb + b * 128 + lane * 4);
    float2 e01 = __half22float2(*(half2*)&eu.x);
    float2 e23 = __half22float2(*(half2*)&eu.y);

    // gate logit for (d,e) = lane
    float acc = sBg[lane];
#pragma unroll
    for (int i4 = 0; i4 < 28; i4++) {
        float v0 = __shfl_sync(0xffffffffu, e01.x, i4);
        float v1 = __shfl_sync(0xffffffffu, e01.y, i4);
        float v2 = __shfl_sync(0xffffffffu, e23.x, i4);
        float v3 = __shfl_sync(0xffffffffu, e23.y, i4);
        acc = fmaf(v0, sWg[(i4 * 4 + 0) * 32 + lane], acc);
        acc = fmaf(v1, sWg[(i4 * 4 + 1) * 32 + lane], acc);
        acc = fmaf(v2, sWg[(i4 * 4 + 2) * 32 + lane], acc);
        acc = fmaf(v3, sWg[(i4 * 4 + 3) * 32 + lane], acc);
    }
    {   // k = 112 lives in lane 28, element 0
        float v = __shfl_sync(0xffffffffu, e01.x, 28);
        acc = fmaf(v, sWg[112 * 32 + lane], acc);
    }

    // softmax over e (4-lane groups)
    float m = acc;
    m = fmaxf(m, __shfl_xor_sync(0xffffffffu, m, 1));
    m = fmaxf(m, __shfl_xor_sync(0xffffffffu, m, 2));
    float ex = expf(acc - m);
    float ssum = ex + __shfl_xor_sync(0xffffffffu, ex, 1);
    ssum += __shfl_xor_sync(0xffffffffu, ssum, 2);
    sG[w][lane] = ex / ssum;
    __syncwarp();

    float gt[8][4];
#pragma unroll
    for (int d = 0; d < 8; d++)
#pragma unroll
        for (int e = 0; e < 4; e++) gt[d][e] = sG[w][d * 4 + e];

    // mixture: lane covers c = lane, +32, +64, +96
#pragma unroll
    for (int ch = 0; ch < 4; ch++) {
        int c = ch * 32 + lane;
        float fe[4];
        if (c < 113) {
#pragma unroll
            for (int e = 0; e < 4; e++) {
                float x = __half2float(fea[((long long)e * B + b) * 128 + c]);
                fe[e] = fmaxf(fmaf(x, g_bnA[1][e * 113 + c], g_bnC[1][e * 113 + c]), 0.f);
            }
        } else {
            fe[0] = fe[1] = fe[2] = fe[3] = 0.f;
        }
#pragma unroll
        for (int d = 0; d < 8; d++) {
            float t = gt[d][0] * fe[0] + gt[d][1] * fe[1] + gt[d][2] * fe[2] + gt[d][3] * fe[3];
            task[((long long)d * B + b) * 128 + c] = __float2half_rn((c < 113) ? t : 0.f);
        }
    }
}

// final: per b, pick domain tower, BN+ReLU on t2 (fp16), dot Wt3, sigmoid
__global__ void final_kernel(const __half* __restrict__ t2,
                             const float* __restrict__ Wt3,
                             const float* __restrict__ bt3,
                             const int* __restrict__ dom,
                             float* __restrict__ out, int B) {
    int gid = blockIdx.x * blockDim.x + threadIdx.x;
    int b = gid >> 5, lane = gid & 31;
    if (b >= B) return;
    int d = g_domIsI64 ? (int)(((const long long*)dom)[b]) : dom[b];
    uint2 u = reinterpret_cast<const uint2*>(t2 + ((long long)d * B + b) * 128)[lane];
    float2 x01 = __half22float2(*(half2*)&u.x);
    float2 x23 = __half22float2(*(half2*)&u.y);
    float4 aa = *reinterpret_cast<const float4*>(&g_bnA[3][d * 128 + lane * 4]);
    float4 cc = *reinterpret_cast<const float4*>(&g_bnC[3][d * 128 + lane * 4]);
    float4 w  = reinterpret_cast<const float4*>(Wt3 + d * 128)[lane];
    float s = fmaxf(fmaf(x01.x, aa.x, cc.x), 0.f) * w.x
            + fmaxf(fmaf(x01.y, aa.y, cc.y), 0.f) * w.y
            + fmaxf(fmaf(x23.x, aa.z, cc.z), 0.f) * w.z
            + fmaxf(fmaf(x23.y, aa.w, cc.w), 0.f) * w.w;
#pragma unroll
    for (int o = 16; o; o >>= 1) s += __shfl_xor_sync(0xffffffffu, s, o);
    if (lane == 0) out[b] = 1.f / (1.f + expf(-(s + bt3[d])));
}

// ---------------- host ----------------
extern "C" void kernel_launch(void* const* d_in, const int* in_sizes, int n_in,
                              void* d_out, int out_size) {
    const int B = 131072;
    int domIdx = -1;
    for (int i = 0; i < n_in; i++)
        if (in_sizes[i] == B) { domIdx = i; break; }

    const float* ptrs[21];
    int pi = 0;
    for (int i = 0; i < n_in && pi < 21; i++) {
        if (i == domIdx) continue;
        ptrs[pi++] = (const float*)d_in[i];
    }
    const float* emb = ptrs[0];
    const float* We1 = ptrs[1],  *be1 = ptrs[2],  *eg1 = ptrs[3],  *eb1 = ptrs[4];
    const float* We2 = ptrs[5],  *be2 = ptrs[6],  *eg2 = ptrs[7],  *eb2 = ptrs[8];
    const float* Wg  = ptrs[9],  *bg  = ptrs[10];
    const float* Wt1 = ptrs[11], *bt1 = ptrs[12], *tg1 = ptrs[13], *tb1 = ptrs[14];
    const float* Wt2 = ptrs[15], *bt2 = ptrs[16], *tg2 = ptrs[17], *tb2 = ptrs[18];
    const float* Wt3 = ptrs[19], *bt3 = ptrs[20];
    const int* dom = (const int*)d_in[domIdx];
    float* out = (float*)d_out;

    __half *p_emb, *p_h1, *p_fea, *p_task, *p_t1, *p_We1t, *p_We2t, *p_Wt1t, *p_Wt2t;
    cudaGetSymbolAddress((void**)&p_emb, g_emb);
    cudaGetSymbolAddress((void**)&p_h1,  g_h1);
    cudaGetSymbolAddress((void**)&p_fea, g_fea);
    cudaGetSymbolAddress((void**)&p_task, g_task);
    cudaGetSymbolAddress((void**)&p_t1,  g_t1);
    cudaGetSymbolAddress((void**)&p_We1t, g_We1t);
    cudaGetSymbolAddress((void**)&p_We2t, g_We2t);
    cudaGetSymbolAddress((void**)&p_Wt1t, g_Wt1t);
    cudaGetSymbolAddress((void**)&p_Wt2t, g_Wt2t);

    cudaFuncSetAttribute(gemm_f16<false, false>, cudaFuncAttributeMaxDynamicSharedMemorySize, SMEM_BYTES);
    cudaFuncSetAttribute(gemm_f16<true,  false>, cudaFuncAttributeMaxDynamicSharedMemorySize, SMEM_BYTES);
    cudaFuncSetAttribute(gemm_f16<true,  true >, cudaFuncAttributeMaxDynamicSharedMemorySize, SMEM_BYTES);

    const float invB = 1.f / (float)B;

    // (1)(2)(3) prep: emb->fp16 pad, weights transpose+fp16, stats zero, dom probe
    prep_emb<<<(B * 32) / 256, 256>>>(emb);
    prep_expert<<<dim3(128, 4, 2), 256>>>(We1, We2);
    prep_tower<<<dim3(128, 8, 2), 256>>>(Wt1, Wt2, dom);

    // (4) expert layer 1: g_emb [B,128] x We1t -> h1 fp16   <-- ncu lands here
    gemm_f16<false, false><<<dim3(2, B / 128, 4), 256, SMEM_BYTES>>>(
        p_emb, 0LL, 128, 128, p_We1t, 32768LL, 128, be1,
        nullptr, nullptr, 0, invB, p_h1, (long long)B * 256, 256, 256, 0, nullptr);

    // (5) expert layer 2 (inline BN0): BN+ReLU(h1) x We2t -> fea fp16
    gemm_f16<true, false><<<dim3(1, B / 128, 4), 256, SMEM_BYTES>>>(
        p_h1, (long long)B * 256, 256, 256, p_We2t, 32768LL, 256, be2,
        eg1, eb1, 0, invB, p_fea, (long long)B * 128, 128, 113, 1, nullptr);

    // (6) finalize stage 1 (consumed by gates_task_v2)
    finalize_kernel<<<2, 256>>>(1, eg2, eb2, 4 * 113, invB);

    // (7) gates + mixture -> task fp16 (8 samples per block, Wg staged in smem)
    gates_task_v2<<<B / 8, 256>>>(p_emb, Wg, bg, p_fea, p_task, B);

    // (8) tower layer 1: task x Wt1t -> t1 fp16
    gemm_f16<false, false><<<dim3(2, B / 128, 8), 256, SMEM_BYTES>>>(
        p_task, (long long)B * 128, 128, 128, p_Wt1t, 32768LL, 128, bt1,
        nullptr, nullptr, 0, invB, p_t1, (long long)B * 256, 256, 256, 2, nullptr);

    // (9) tower layer 2 (inline BN2, selective store): BN+ReLU(t1) x Wt2t -> t2 (reuses g_h1)
    gemm_f16<true, true><<<dim3(1, B / 128, 8), 256, SMEM_BYTES>>>(
        p_t1, (long long)B * 256, 256, 256, p_Wt2t, 32768LL, 256, bt2,
        tg1, tb1, 2, invB, p_h1, (long long)B * 128, 128, 128, 3, dom);

    // (10) finalize stage 3 (consumed elementwise by final)
    finalize_kernel<<<4, 256>>>(3, tg2, tb2, 8 * 128, invB);

    // (11) final: gather domain, BN+ReLU, dot Wt3, sigmoid
    final_kernel<<<(B * 32) / 256, 256>>>(p_h1, Wt3, bt3, dom, out, B);
}